// round 4
// baseline (speedup 1.0000x reference)
#include <cuda_runtime.h>

// TinyLSTM: B=64, T=2048, H=256, V=256
// out = [ logits (64*2048*256) | h_n (64*256) | c_n (64*256) ]  (float32)

#define T_SEQ 2048
#define BATCH 64
#define HID   256
#define G4    1024
#define VOCAB 256

#define LOGITS_ELEMS (BATCH * T_SEQ * HID)

// scratch (static device arrays; no allocation)
__device__ float        g_xtab[VOCAB * G4];   // [v][r] = W_ih[r][v] + b_ih[r] + b_hh[r]
__device__ float        g_fcwt[HID * VOCAB];  // [k][c] = fc_W[c][k]
__device__ unsigned int g_bar[16];            // per-batch-group step counters

// ---- packed f32x2 helpers ----
__device__ __forceinline__ unsigned long long pk2(float a, float b) {
    unsigned long long r;
    asm("mov.b64 %0, {%1, %2};" : "=l"(r) : "f"(a), "f"(b));
    return r;
}
__device__ __forceinline__ void upk2(unsigned long long v, float& a, float& b) {
    asm("mov.b64 {%0, %1}, %2;" : "=f"(a), "=f"(b) : "l"(v));
}
__device__ __forceinline__ void ffma2(unsigned long long& d, unsigned long long a, unsigned long long b) {
    asm("fma.rn.f32x2 %0, %1, %2, %0;" : "+l"(d) : "l"(a), "l"(b));
}

// =====================================================================
// Phase 0: build token table (biases folded), transpose fc_W, reset bars
// =====================================================================
__global__ void prep_kernel(const float* __restrict__ W_ih,
                            const float* __restrict__ b_ih,
                            const float* __restrict__ b_hh,
                            const float* __restrict__ fc_W) {
    int idx = blockIdx.x * blockDim.x + threadIdx.x;   // up to 262144
    if (idx < VOCAB * G4) {
        int v = idx >> 10;
        int r = idx & 1023;
        g_xtab[v * G4 + r] = W_ih[r * VOCAB + v] + b_ih[r] + b_hh[r];
    }
    if (idx < HID * VOCAB) {
        int k = idx >> 8;
        int c = idx & 255;
        g_fcwt[k * VOCAB + c] = fc_W[c * HID + k];
    }
    if (idx < 16) g_bar[idx] = 0u;
}

// =====================================================================
// Phase 1: persistent LSTM recurrence.
// 128 CTAs = 16 batch-groups (4 batches each) x 8 gate-slice members
// (32 h-indices each -> 128 gate rows). W_hh slice lives in registers.
// h(t) is exchanged through the hs region of d_out (the data the final
// FC needs anyway), synchronized by a per-group global counter barrier.
// =====================================================================
__global__ void __launch_bounds__(512, 1)
lstm_kernel(const int* __restrict__ x,            // tokens are int32 (JAX x64 off)
            const float* __restrict__ W_hh,
            float* __restrict__ out) {
    __shared__ __align__(16) float sh_h[4][256];   // h(t-1) for this group's 4 batches
    __shared__ float sh_gates[128][5];             // [gate*32+j][b], padded
    __shared__ float sh_c[4][32];                  // cell state (CTA-private)
    __shared__ int   sh_tok[4];

    const int cta    = blockIdx.x;
    const int gb     = cta >> 3;       // batch group 0..15
    const int m      = cta & 7;        // gate-slice member 0..7
    const int b_base = gb * 4;
    const int j_base = m * 32;

    const int tid  = threadIdx.x;
    const int r    = tid >> 2;         // local gate row 0..127
    const int q    = tid & 3;          // k-chunk 0..3 (64 k each)
    const int gate = r >> 5;
    const int jj   = r & 31;
    const int r_global = gate * 256 + j_base + jj;   // row of W_hh / xtab

    // --- load W_hh slice into registers as f32x2 pairs (once) ---
    unsigned long long w2[32];
    {
        const float4* wr = reinterpret_cast<const float4*>(W_hh + r_global * HID + q * 64);
#pragma unroll
        for (int i = 0; i < 16; i++) {
            float4 v = wr[i];
            w2[2 * i]     = pk2(v.x, v.y);
            w2[2 * i + 1] = pk2(v.z, v.w);
        }
    }
    if (tid < 128) sh_c[tid >> 5][tid & 31] = 0.0f;

    float* hsout = out;                                        // [B][T][H]
    float* hN    = out + (size_t)LOGITS_ELEMS;                 // [B][H]
    float* cN    = hN + BATCH * HID;                           // [B][H]
    unsigned int* bar = &g_bar[gb];

    for (int t = 0; t < T_SEQ; t++) {
        // ---- stage h(t-1) + tokens into smem ----
        if (tid < 4) sh_tok[tid] = x[(b_base + tid) * T_SEQ + t] & 255;
        if (tid < 256) {
            int bb = tid >> 6, k4 = tid & 63;
            float4 hv;
            if (t == 0) {
                hv = make_float4(0.f, 0.f, 0.f, 0.f);
            } else {
                hv = *reinterpret_cast<const float4*>(
                    &hsout[((size_t)(b_base + bb) * T_SEQ + (t - 1)) * HID + k4 * 4]);
            }
            *reinterpret_cast<float4*>(&sh_h[bb][k4 * 4]) = hv;
        }
        __syncthreads();

        // ---- token-table contributions (hidden behind matmul) ----
        float xg0 = 0.f, xg1 = 0.f, xg2 = 0.f, xg3 = 0.f;
        if (q == 0) {
            xg0 = __ldg(&g_xtab[sh_tok[0] * G4 + r_global]);
            xg1 = __ldg(&g_xtab[sh_tok[1] * G4 + r_global]);
            xg2 = __ldg(&g_xtab[sh_tok[2] * G4 + r_global]);
            xg3 = __ldg(&g_xtab[sh_tok[3] * G4 + r_global]);
        }

        // ---- partial dot products: 4 batches x 64 k, weights in regs ----
        float acc[4];
#pragma unroll
        for (int bb = 0; bb < 4; bb++) {
            unsigned long long a2 = 0ull, b2 = 0ull;
            const ulonglong2* hp = reinterpret_cast<const ulonglong2*>(&sh_h[bb][q * 64]);
#pragma unroll
            for (int i = 0; i < 16; i++) {
                ulonglong2 hv = hp[i];
                ffma2(a2, w2[2 * i],     hv.x);
                ffma2(b2, w2[2 * i + 1], hv.y);
            }
            float a0, a1, c0, c1;
            upk2(a2, a0, a1);
            upk2(b2, c0, c1);
            acc[bb] = (a0 + a1) + (c0 + c1);
        }

        // ---- reduce across the 4 k-chunks (adjacent lanes) ----
#pragma unroll
        for (int bb = 0; bb < 4; bb++) {
            acc[bb] += __shfl_xor_sync(0xffffffffu, acc[bb], 1);
            acc[bb] += __shfl_xor_sync(0xffffffffu, acc[bb], 2);
        }
        if (q == 0) {
            sh_gates[r][0] = acc[0] + xg0;
            sh_gates[r][1] = acc[1] + xg1;
            sh_gates[r][2] = acc[2] + xg2;
            sh_gates[r][3] = acc[3] + xg3;
        }
        __syncthreads();

        // ---- gate nonlinearities + state update (128 threads) ----
        if (tid < 128) {
            int bb = tid >> 5, j2 = tid & 31;
            float iv = sh_gates[j2][bb];
            float fv = sh_gates[32 + j2][bb];
            float gv = sh_gates[64 + j2][bb];
            float ov = sh_gates[96 + j2][bb];
            float is = __fdividef(1.f, 1.f + __expf(-iv));
            float fs = __fdividef(1.f, 1.f + __expf(-fv));
            float gt = 1.f - __fdividef(2.f, 1.f + __expf(2.f * gv));
            float os = __fdividef(1.f, 1.f + __expf(-ov));
            float cv = fs * sh_c[bb][j2] + is * gt;
            sh_c[bb][j2] = cv;
            float ct = 1.f - __fdividef(2.f, 1.f + __expf(2.f * cv));
            float hv = os * ct;
            hsout[((size_t)(b_base + bb) * T_SEQ + t) * HID + j_base + j2] = hv;
            if (t == T_SEQ - 1) {
                hN[(b_base + bb) * HID + j_base + j2] = hv;
                cN[(b_base + bb) * HID + j_base + j2] = cv;
            }
        }

        // ---- group barrier (monotonic counter; release/acquire via fences) ----
        __threadfence();
        __syncthreads();
        if (tid == 0) {
            atomicAdd(bar, 1u);
            unsigned int target = 8u * (unsigned int)(t + 1);
            while (atomicAdd(bar, 0u) < target) { }
            __threadfence();
        }
        __syncthreads();
    }
}

// =====================================================================
// Phase 2: logits = hs @ fc_W^T + fc_b, in-place over the hs region.
// Each CTA: 32 rows, 128 threads, 8x8 register tile per thread, f32x2.
// Static shared (< 48 KB): K-slab of 32 for both weights and h rows.
// =====================================================================
#define FC_KSLAB 32
#define FC_WPAD  260

__global__ void __launch_bounds__(128)
fc_kernel(float* __restrict__ out, const float* __restrict__ fc_b) {
    __shared__ __align__(16) float wslab[FC_KSLAB][FC_WPAD];  // [k][c], ~33 KB
    __shared__ float sh_h[32][FC_KSLAB + 1];                  // [row][k], 4.1 KB

    const int tid = threadIdx.x;
    const int rg  = tid >> 5;            // warp -> rows rg*8 .. +8
    const int cg  = tid & 31;            // cols cg*8 .. +8
    const size_t row_base = (size_t)blockIdx.x * 32;

    unsigned long long acc[8][4];
#pragma unroll
    for (int a = 0; a < 8; a++)
#pragma unroll
        for (int b = 0; b < 4; b++) acc[a][b] = 0ull;

    for (int k0 = 0; k0 < HID; k0 += FC_KSLAB) {
        __syncthreads();
        // weights slab: 32 k x 256 c
        for (int i = tid; i < FC_KSLAB * 64; i += 128) {
            int kk = i >> 6, c4 = i & 63;
            *reinterpret_cast<float4*>(&wslab[kk][c4 * 4]) =
                *reinterpret_cast<const float4*>(&g_fcwt[(size_t)(k0 + kk) * VOCAB + c4 * 4]);
        }
        // h slab: 32 rows x 32 k
        for (int i = tid; i < 32 * (FC_KSLAB / 4); i += 128) {
            int rr = i >> 3, k4 = i & 7;
            float4 v = *reinterpret_cast<const float4*>(
                &out[(row_base + rr) * HID + k0 + k4 * 4]);
            sh_h[rr][k4 * 4 + 0] = v.x;
            sh_h[rr][k4 * 4 + 1] = v.y;
            sh_h[rr][k4 * 4 + 2] = v.z;
            sh_h[rr][k4 * 4 + 3] = v.w;
        }
        __syncthreads();
#pragma unroll 4
        for (int kk = 0; kk < FC_KSLAB; kk++) {
            ulonglong2 wv0 = *reinterpret_cast<const ulonglong2*>(&wslab[kk][cg * 8]);
            ulonglong2 wv1 = *reinterpret_cast<const ulonglong2*>(&wslab[kk][cg * 8 + 4]);
#pragma unroll
            for (int rr = 0; rr < 8; rr++) {
                float hv = sh_h[rg * 8 + rr][kk];
                unsigned long long hp = pk2(hv, hv);
                ffma2(acc[rr][0], hp, wv0.x);
                ffma2(acc[rr][1], hp, wv0.y);
                ffma2(acc[rr][2], hp, wv1.x);
                ffma2(acc[rr][3], hp, wv1.y);
            }
        }
    }

    float bias[8];
#pragma unroll
    for (int cc = 0; cc < 8; cc++) bias[cc] = fc_b[cg * 8 + cc];
#pragma unroll
    for (int rr = 0; rr < 8; rr++) {
        float v[8];
        upk2(acc[rr][0], v[0], v[1]);
        upk2(acc[rr][1], v[2], v[3]);
        upk2(acc[rr][2], v[4], v[5]);
        upk2(acc[rr][3], v[6], v[7]);
        float4 o0 = make_float4(v[0] + bias[0], v[1] + bias[1], v[2] + bias[2], v[3] + bias[3]);
        float4 o1 = make_float4(v[4] + bias[4], v[5] + bias[5], v[6] + bias[6], v[7] + bias[7]);
        float* dst = out + (row_base + rg * 8 + rr) * VOCAB + cg * 8;
        *reinterpret_cast<float4*>(dst)     = o0;
        *reinterpret_cast<float4*>(dst + 4) = o1;
    }
}

// =====================================================================
extern "C" void kernel_launch(void* const* d_in, const int* in_sizes, int n_in,
                              void* d_out, int out_size) {
    (void)in_sizes; (void)n_in; (void)out_size;
    const int*   x      = (const int*)d_in[0];     // int32 tokens (JAX x64 disabled)
    const float* W_ih   = (const float*)d_in[1];
    const float* W_hh   = (const float*)d_in[2];
    const float* b_ih   = (const float*)d_in[3];
    const float* b_hh   = (const float*)d_in[4];
    const float* fc_W   = (const float*)d_in[5];
    const float* fc_b   = (const float*)d_in[6];
    float* out = (float*)d_out;

    prep_kernel<<<1024, 256>>>(W_ih, b_ih, b_hh, fc_W);
    lstm_kernel<<<128, 512>>>(x, W_hh, out);
    fc_kernel<<<(BATCH * T_SEQ) / 32, 128>>>(out, fc_b);
}

// round 5
// speedup vs baseline: 3.7395x; 3.7395x over previous
#include <cuda_runtime.h>

// TinyLSTM: B=64, T=2048, H=256, V=256
// out = [ logits (64*2048*256) | h_n (64*256) | c_n (64*256) ]  (float32)

#define T_SEQ 2048
#define BATCH 64
#define HID   256
#define G4    1024
#define VOCAB 256

#define LOGITS_ELEMS (BATCH * T_SEQ * HID)

#define HPAD 132   // skewed chunk stride (floats): chunk q at q*132 -> disjoint banks

// scratch (static device arrays; no allocation)
__device__ float        g_xtab[VOCAB * G4];   // [v][r] = W_ih[r][v] + b_ih[r] + b_hh[r]
__device__ float        g_fcwt[HID * VOCAB];  // [k][c] = fc_W[c][k]
__device__ unsigned int g_bar[16];            // per-batch-group step counters

// ---- packed f32x2 helpers ----
__device__ __forceinline__ unsigned long long pk2(float a, float b) {
    unsigned long long r;
    asm("mov.b64 %0, {%1, %2};" : "=l"(r) : "f"(a), "f"(b));
    return r;
}
__device__ __forceinline__ void upk2(unsigned long long v, float& a, float& b) {
    asm("mov.b64 {%0, %1}, %2;" : "=f"(a), "=f"(b) : "l"(v));
}
__device__ __forceinline__ void ffma2(unsigned long long& d, unsigned long long a, unsigned long long b) {
    asm("fma.rn.f32x2 %0, %1, %2, %0;" : "+l"(d) : "l"(a), "l"(b));
}
// L2-only vector load (bypass L1: exchange data is produced by peer SMs each step)
__device__ __forceinline__ float4 ldcg4(const float* p) {
    float4 v;
    asm volatile("ld.global.cg.v4.f32 {%0,%1,%2,%3}, [%4];"
                 : "=f"(v.x), "=f"(v.y), "=f"(v.z), "=f"(v.w) : "l"(p));
    return v;
}
__device__ __forceinline__ void red_release_add(unsigned int* p, unsigned int v) {
    asm volatile("red.release.gpu.global.add.u32 [%0], %1;" :: "l"(p), "r"(v) : "memory");
}
__device__ __forceinline__ unsigned int ld_acquire(const unsigned int* p) {
    unsigned int v;
    asm volatile("ld.acquire.gpu.global.u32 %0, [%1];" : "=r"(v) : "l"(p) : "memory");
    return v;
}

// =====================================================================
// Phase 0: build token table (biases folded), transpose fc_W, reset bars
// =====================================================================
__global__ void prep_kernel(const float* __restrict__ W_ih,
                            const float* __restrict__ b_ih,
                            const float* __restrict__ b_hh,
                            const float* __restrict__ fc_W) {
    int idx = blockIdx.x * blockDim.x + threadIdx.x;   // up to 262144
    if (idx < VOCAB * G4) {
        int v = idx >> 10;
        int r = idx & 1023;
        g_xtab[v * G4 + r] = W_ih[r * VOCAB + v] + b_ih[r] + b_hh[r];
    }
    if (idx < HID * VOCAB) {
        int k = idx >> 8;
        int c = idx & 255;
        g_fcwt[k * VOCAB + c] = fc_W[c * HID + k];
    }
    if (idx < 16) g_bar[idx] = 0u;
}

// =====================================================================
// Phase 1: persistent LSTM recurrence.
// 128 CTAs = 16 batch-groups (4 batches each) x 8 gate-slice members
// (32 h-indices -> 128 gate rows each). 256 threads/CTA = 128 rows x
// 2 K-chunks (128 wide). W_hh slice register-resident: w2[64] = 128 regs
// (launch_bounds(256,1) -> 256-reg budget, no spills).
// h(t) exchanged through the hs region of d_out (the FC input anyway),
// synchronized by a per-group fence-free release/acquire counter.
// =====================================================================
__global__ void __launch_bounds__(256, 1)
lstm_kernel(const int* __restrict__ x,
            const float* __restrict__ W_hh,
            float* __restrict__ out) {
    __shared__ __align__(16) float sh_h[4][2 * HPAD]; // h(t-1), skewed chunks
    __shared__ float sh_gates[128][5];                // [gate*32+j][b], padded
    __shared__ float sh_c[4][32];                     // cell state (CTA-private)
    __shared__ int   sh_tok[2][4];                    // double-buffered tokens

    const int cta    = blockIdx.x;
    const int gb     = cta >> 3;       // batch group 0..15
    const int m      = cta & 7;        // gate-slice member 0..7
    const int b_base = gb * 4;
    const int j_base = m * 32;

    const int tid  = threadIdx.x;
    const int r    = tid >> 1;         // local gate row 0..127
    const int q    = tid & 1;          // k-chunk 0..1 (128 k each)
    const int gate = r >> 5;
    const int jj   = r & 31;
    const int r_global = gate * 256 + j_base + jj;   // row of W_hh / xtab

    // --- load W_hh slice into registers as f32x2 pairs (once) ---
    unsigned long long w2[64];
    {
        const float4* wr = reinterpret_cast<const float4*>(W_hh + r_global * HID + q * 128);
#pragma unroll
        for (int i = 0; i < 32; i++) {
            float4 v = wr[i];
            w2[2 * i]     = pk2(v.x, v.y);
            w2[2 * i + 1] = pk2(v.z, v.w);
        }
    }
    if (tid < 128) sh_c[tid >> 5][tid & 31] = 0.0f;
    if (tid < 4)   sh_tok[0][tid] = x[(b_base + tid) * T_SEQ + 0] & 255;

    float* hsout = out;                                        // [B][T][H]
    float* hN    = out + (size_t)LOGITS_ELEMS;                 // [B][H]
    float* cN    = hN + BATCH * HID;                           // [B][H]
    unsigned int* bar = &g_bar[gb];

    for (int t = 0; t < T_SEQ; t++) {
        const int pb = t & 1;

        // ---- stage h(t-1) into skewed smem (L2-only loads) ----
        {
            int bb = tid >> 6, k4 = tid & 63;                  // k = k4*4
            float4 hv;
            if (t == 0) {
                hv = make_float4(0.f, 0.f, 0.f, 0.f);
            } else {
                hv = ldcg4(&hsout[((size_t)(b_base + bb) * T_SEQ + (t - 1)) * HID + k4 * 4]);
            }
            int qs = k4 >> 5, j = (k4 & 31) * 4;
            *reinterpret_cast<float4*>(&sh_h[bb][qs * HPAD + j]) = hv;
        }
        // prefetch tokens for t+1 (off the critical path)
        if (tid < 4 && t + 1 < T_SEQ)
            sh_tok[pb ^ 1][tid] = x[(b_base + tid) * T_SEQ + t + 1] & 255;
        __syncthreads();

        // ---- token-table contributions (issued early, consumed late) ----
        float xg0 = 0.f, xg1 = 0.f, xg2 = 0.f, xg3 = 0.f;
        if (q == 0) {
            xg0 = __ldg(&g_xtab[sh_tok[pb][0] * G4 + r_global]);
            xg1 = __ldg(&g_xtab[sh_tok[pb][1] * G4 + r_global]);
            xg2 = __ldg(&g_xtab[sh_tok[pb][2] * G4 + r_global]);
            xg3 = __ldg(&g_xtab[sh_tok[pb][3] * G4 + r_global]);
        }

        // ---- partial dot products: 4 batches x 128 k, weights in regs ----
        float acc[4];
#pragma unroll
        for (int bb = 0; bb < 4; bb++) {
            unsigned long long a2 = 0ull, b2 = 0ull;
            const ulonglong2* hp = reinterpret_cast<const ulonglong2*>(&sh_h[bb][q * HPAD]);
#pragma unroll
            for (int i = 0; i < 32; i++) {
                ulonglong2 hv = hp[i];
                ffma2(a2, w2[2 * i],     hv.x);
                ffma2(b2, w2[2 * i + 1], hv.y);
            }
            float a0, a1, c0, c1;
            upk2(a2, a0, a1);
            upk2(b2, c0, c1);
            acc[bb] = (a0 + a1) + (c0 + c1);
        }

        // ---- reduce across the 2 k-chunks (adjacent lanes) ----
#pragma unroll
        for (int bb = 0; bb < 4; bb++)
            acc[bb] += __shfl_xor_sync(0xffffffffu, acc[bb], 1);
        if (q == 0) {
            sh_gates[r][0] = acc[0] + xg0;
            sh_gates[r][1] = acc[1] + xg1;
            sh_gates[r][2] = acc[2] + xg2;
            sh_gates[r][3] = acc[3] + xg3;
        }
        __syncthreads();

        // ---- gate nonlinearities + state update (128 threads) ----
        if (tid < 128) {
            int bb = tid >> 5, j2 = tid & 31;
            float iv = sh_gates[j2][bb];
            float fv = sh_gates[32 + j2][bb];
            float gv = sh_gates[64 + j2][bb];
            float ov = sh_gates[96 + j2][bb];
            float is = __fdividef(1.f, 1.f + __expf(-iv));
            float fs = __fdividef(1.f, 1.f + __expf(-fv));
            float gt = 1.f - __fdividef(2.f, 1.f + __expf(2.f * gv));
            float os = __fdividef(1.f, 1.f + __expf(-ov));
            float cv = fs * sh_c[bb][j2] + is * gt;
            sh_c[bb][j2] = cv;
            float ct = 1.f - __fdividef(2.f, 1.f + __expf(2.f * cv));
            float hv = os * ct;
            hsout[((size_t)(b_base + bb) * T_SEQ + t) * HID + j_base + j2] = hv;
            if (t == T_SEQ - 1) {
                hN[(b_base + bb) * HID + j_base + j2] = hv;
                cN[(b_base + bb) * HID + j_base + j2] = cv;
            }
        }

        // ---- group barrier: fence-free release/acquire monotonic counter ----
        __syncthreads();                       // h stores of all threads precede arrive
        if (tid == 0) {
            red_release_add(bar, 1u);          // publish (orders CTA's stores, gpu scope)
            const unsigned int target = 8u * (unsigned int)(t + 1);
            while (ld_acquire(bar) < target) { }
        }
        __syncthreads();                       // acquire propagates to all threads
    }
}

// =====================================================================
// Phase 2: logits = hs @ fc_W^T + fc_b, in-place over the hs region.
// Each CTA: 32 rows, 128 threads, 8x8 register tile per thread, f32x2.
// =====================================================================
#define FC_KSLAB 32
#define FC_WPAD  260

__global__ void __launch_bounds__(128)
fc_kernel(float* __restrict__ out, const float* __restrict__ fc_b) {
    __shared__ __align__(16) float wslab[FC_KSLAB][FC_WPAD];  // ~33 KB
    __shared__ float sh_h[32][FC_KSLAB + 1];                  // 4.1 KB

    const int tid = threadIdx.x;
    const int rg  = tid >> 5;            // warp -> rows rg*8 .. +8
    const int cg  = tid & 31;            // cols cg*8 .. +8
    const size_t row_base = (size_t)blockIdx.x * 32;

    unsigned long long acc[8][4];
#pragma unroll
    for (int a = 0; a < 8; a++)
#pragma unroll
        for (int b = 0; b < 4; b++) acc[a][b] = 0ull;

    for (int k0 = 0; k0 < HID; k0 += FC_KSLAB) {
        __syncthreads();
        for (int i = tid; i < FC_KSLAB * 64; i += 128) {
            int kk = i >> 6, c4 = i & 63;
            *reinterpret_cast<float4*>(&wslab[kk][c4 * 4]) =
                *reinterpret_cast<const float4*>(&g_fcwt[(size_t)(k0 + kk) * VOCAB + c4 * 4]);
        }
        for (int i = tid; i < 32 * (FC_KSLAB / 4); i += 128) {
            int rr = i >> 3, k4 = i & 7;
            float4 v = *reinterpret_cast<const float4*>(
                &out[(row_base + rr) * HID + k0 + k4 * 4]);
            sh_h[rr][k4 * 4 + 0] = v.x;
            sh_h[rr][k4 * 4 + 1] = v.y;
            sh_h[rr][k4 * 4 + 2] = v.z;
            sh_h[rr][k4 * 4 + 3] = v.w;
        }
        __syncthreads();
#pragma unroll 4
        for (int kk = 0; kk < FC_KSLAB; kk++) {
            ulonglong2 wv0 = *reinterpret_cast<const ulonglong2*>(&wslab[kk][cg * 8]);
            ulonglong2 wv1 = *reinterpret_cast<const ulonglong2*>(&wslab[kk][cg * 8 + 4]);
#pragma unroll
            for (int rr = 0; rr < 8; rr++) {
                float hv = sh_h[rg * 8 + rr][kk];
                unsigned long long hp = pk2(hv, hv);
                ffma2(acc[rr][0], hp, wv0.x);
                ffma2(acc[rr][1], hp, wv0.y);
                ffma2(acc[rr][2], hp, wv1.x);
                ffma2(acc[rr][3], hp, wv1.y);
            }
        }
    }

    float bias[8];
#pragma unroll
    for (int cc = 0; cc < 8; cc++) bias[cc] = fc_b[cg * 8 + cc];
#pragma unroll
    for (int rr = 0; rr < 8; rr++) {
        float v[8];
        upk2(acc[rr][0], v[0], v[1]);
        upk2(acc[rr][1], v[2], v[3]);
        upk2(acc[rr][2], v[4], v[5]);
        upk2(acc[rr][3], v[6], v[7]);
        float4 o0 = make_float4(v[0] + bias[0], v[1] + bias[1], v[2] + bias[2], v[3] + bias[3]);
        float4 o1 = make_float4(v[4] + bias[4], v[5] + bias[5], v[6] + bias[6], v[7] + bias[7]);
        float* dst = out + (row_base + rg * 8 + rr) * VOCAB + cg * 8;
        *reinterpret_cast<float4*>(dst)     = o0;
        *reinterpret_cast<float4*>(dst + 4) = o1;
    }
}

// =====================================================================
extern "C" void kernel_launch(void* const* d_in, const int* in_sizes, int n_in,
                              void* d_out, int out_size) {
    (void)in_sizes; (void)n_in; (void)out_size;
    const int*   x      = (const int*)d_in[0];     // int32 tokens
    const float* W_ih   = (const float*)d_in[1];
    const float* W_hh   = (const float*)d_in[2];
    const float* b_ih   = (const float*)d_in[3];
    const float* b_hh   = (const float*)d_in[4];
    const float* fc_W   = (const float*)d_in[5];
    const float* fc_b   = (const float*)d_in[6];
    float* out = (float*)d_out;

    prep_kernel<<<1024, 256>>>(W_ih, b_ih, b_hh, fc_W);
    lstm_kernel<<<128, 256>>>(x, W_hh, out);
    fc_kernel<<<(BATCH * T_SEQ) / 32, 128>>>(out, fc_b);
}